// round 3
// baseline (speedup 1.0000x reference)
#include <cuda_runtime.h>
#include <cstdint>

#define WINDOW 40
#define EE 8
#define NSTOCK 8000
#define TDIM 64
#define FDIM 64
#define INCH 144
#define LOUT 36

// rank scratch: [col][n] then transposed to [n][col]
__device__ float g_rank[WINDOW * EE * NSTOCK];      // [col][n]
__device__ float g_rank_t[NSTOCK * WINDOW * EE];    // [n][col]

// ---------------------------------------------------------------------------
// Kernel A: exact descending rank (stable, tie-break by index) per column.
// 32768 bins, keys in registers, in-place prefix over hist.
// smem: pack 64000 | hist 131072 | rank_sm 32000  = 227072 B
// ---------------------------------------------------------------------------
#define NB 32768
#define RT 1024
#define SMEM_A (64000 + NB * 4 + 32000)

__global__ void __launch_bounds__(RT) rank_kernel(const float* __restrict__ x) {
    extern __shared__ unsigned char smem_raw[];
    unsigned long long* g_pack = (unsigned long long*)smem_raw;          // 64000 B
    unsigned int* hist = (unsigned int*)(smem_raw + 64000);              // 131072 B (hist -> ofs -> ends)
    float* rank_sm = (float*)(smem_raw + 64000 + NB * 4);                // 32000 B

    __shared__ unsigned int wsum[32];

    const int col = blockIdx.x;
    const int tw  = col >> 3;
    const int e   = col & 7;
    const int tid = threadIdx.x;

    // zero hist
    for (int i = tid; i < NB; i += RT) hist[i] = 0u;
    __syncthreads();

    const float* base = x + (24 + tw) * FDIM + e;

    // pass 1: load keys to registers + histogram
    unsigned int rk[8];
    int nvalid = 0;
#pragma unroll
    for (int i = 0; i < 8; i++) {
        int n = tid + i * RT;
        if (n < NSTOCK) {
            unsigned int u = __float_as_uint(__ldg(base + (size_t)n * (TDIM * FDIM)));
            u = (u & 0x80000000u) ? ~u : (u | 0x80000000u);
            rk[i] = u;
            atomicAdd(&hist[u >> 17], 1u);
            nvalid = i + 1;
        }
    }
    __syncthreads();

    // in-place exclusive prefix sum over NB bins (thread owns 32-bin chunk)
    {
        const int CH = NB / RT;              // 32
        const int b0 = tid * CH;
        unsigned int s = 0;
        for (int j = 0; j < CH; j++) s += hist[b0 + j];

        const unsigned int lane = tid & 31u;
        const unsigned int wid  = tid >> 5;
        unsigned int v = s;
#pragma unroll
        for (int o = 1; o < 32; o <<= 1) {
            unsigned int t = __shfl_up_sync(0xFFFFFFFFu, v, o);
            if (lane >= (unsigned)o) v += t;
        }
        if (lane == 31u) wsum[wid] = v;
        __syncthreads();
        if (wid == 0) {
            unsigned int orig = wsum[lane];
            unsigned int w = orig;
#pragma unroll
            for (int o = 1; o < 32; o <<= 1) {
                unsigned int t = __shfl_up_sync(0xFFFFFFFFu, w, o);
                if (lane >= (unsigned)o) w += t;
            }
            wsum[lane] = w - orig;
        }
        __syncthreads();
        unsigned int run = wsum[wid] + (v - s);   // exclusive base for this chunk
        for (int j = 0; j < CH; j++) {
            unsigned int h = hist[b0 + j];
            hist[b0 + j] = run;
            run += h;
        }
    }
    __syncthreads();

    // pass 2: scatter packed (key, inverted-index) grouped by bin (from registers)
#pragma unroll
    for (int i = 0; i < 8; i++) {
        if (i < nvalid) {
            int n = tid + i * RT;
            unsigned int u = rk[i];
            unsigned int p = atomicAdd(&hist[u >> 17], 1u);
            g_pack[p] = ((unsigned long long)u << 16) | (unsigned int)(65535 - n);
        }
    }
    __syncthreads();
    // post-scatter: hist[b] == end offset of bin b; start(b) = hist[b-1]

    // pass 3: exact greater-count within bin (tie-break encoded in packing)
    for (int p = tid; p < NSTOCK; p += RT) {
        unsigned long long pk = g_pack[p];
        unsigned int b = (unsigned int)(pk >> 33);
        unsigned int end = hist[b];
        unsigned int start = b ? hist[b - 1] : 0u;
        unsigned int g = (unsigned int)NSTOCK - end;
        for (unsigned int q = start; q < end; q++)
            g += (g_pack[q] > pk) ? 1u : 0u;
        int idx = 65535 - (int)(pk & 0xFFFFull);
        rank_sm[idx] = (float)g * (1.0f / (float)NSTOCK);
    }
    __syncthreads();

    float* dst = g_rank + (size_t)col * NSTOCK;
    for (int n = tid; n < NSTOCK; n += RT) dst[n] = rank_sm[n];
}

// ---------------------------------------------------------------------------
// Transpose [col][n] -> [n][col] (coalesced both sides)
// ---------------------------------------------------------------------------
__global__ void transpose_kernel() {
    __shared__ float tile[32][33];
    const int c0 = blockIdx.x * 32;
    const int n0 = blockIdx.y * 32;
    const int tx = threadIdx.x, ty = threadIdx.y;
    tile[ty][tx] = g_rank[(size_t)(c0 + ty) * NSTOCK + n0 + tx];
    __syncthreads();
    g_rank_t[(size_t)(n0 + ty) * (WINDOW * EE) + c0 + tx] = tile[tx][ty];
}

// ---------------------------------------------------------------------------
// Kernel B: fused sliding-window stats + conv (only out-channel 127) + linear
// ---------------------------------------------------------------------------
__global__ void __launch_bounds__(256) main_kernel(
    const float* __restrict__ x,
    const float* __restrict__ conv_w,
    const float* __restrict__ conv_b,
    const float* __restrict__ lin_w,
    const float* __restrict__ lin_b,
    float* __restrict__ out)
{
    __shared__ __align__(16) float xe[59][9];            // x[n, 5:64, 0:8], padded
    __shared__ __align__(16) float stats[WINDOW * 64];   // [tw][statid*8 + e]
    __shared__ __align__(16) float rank_row[WINDOW * EE];// [tw*8 + e], 16B-aligned for float4
    __shared__ float partial[5][LOUT];
    __shared__ float fin[LOUT];

    const int n = blockIdx.x;
    const int tid = threadIdx.x;
    const float* xn = x + (size_t)n * (TDIM * FDIM);

    // load xe = x[n, 5:64, 0:8]
    for (int i = tid; i < 59 * 8; i += 256) {
        int tt = i >> 3, ee = i & 7;
        xe[tt][ee] = __ldg(xn + (5 + tt) * FDIM + ee);
    }
    // load rank row (contiguous, float4; both sides 16B aligned: base 256B, stride 1280B)
    {
        const float4* rsrc = (const float4*)(g_rank_t + (size_t)n * (WINDOW * EE));
        for (int i = tid; i < (WINDOW * EE) / 4; i += 256)
            ((float4*)rank_row)[i] = rsrc[i];
    }
    __syncthreads();

    // stats: 320 (tw, e) tasks
    for (int i = tid; i < WINDOW * EE; i += 256) {
        int tw = i >> 3, ee = i & 7;
        int te = 19 + tw;

        float s5 = 0.f, mx5 = -1e30f, mn5 = 1e30f;
#pragma unroll
        for (int j = 0; j < 5; j++) {
            float v = xe[te - 4 + j][ee];
            s5 += v; mx5 = fmaxf(mx5, v); mn5 = fminf(mn5, v);
        }
        float m5 = s5 * 0.2f;
        float var5 = 0.f;
#pragma unroll
        for (int j = 0; j < 5; j++) {
            float d = xe[te - 4 + j][ee] - m5;
            var5 += d * d;
        }
        float sd5 = sqrtf(var5 * 0.25f);

        float s20 = 0.f, mx20 = -1e30f, mn20 = 1e30f;
#pragma unroll
        for (int j = 0; j < 20; j++) {
            float v = xe[te - 19 + j][ee];
            s20 += v; mx20 = fmaxf(mx20, v); mn20 = fminf(mn20, v);
        }
        float m20 = s20 * 0.05f;
        float var20 = 0.f;
#pragma unroll
        for (int j = 0; j < 20; j++) {
            float d = xe[te - 19 + j][ee] - m20;
            var20 += d * d;
        }
        float sd20 = sqrtf(var20 * (1.0f / 19.0f));

        float* st = stats + tw * 64 + ee;
        st[0]  = m5;   st[8]  = sd5;  st[16] = mx5;  st[24] = mn5;
        st[32] = m20;  st[40] = sd20; st[48] = mx20; st[56] = mn20;
    }
    __syncthreads();

    // conv: thread tid < 144 owns input channel tid; 36 accumulators
    float acc[LOUT];
#pragma unroll
    for (int l = 0; l < LOUT; l++) acc[l] = 0.f;

    const int c = tid;
    if (c < INCH) {
        const float* wp = conv_w + 127 * (INCH * 5) + c * 5;
        float w0 = __ldg(wp + 0), w1 = __ldg(wp + 1), w2 = __ldg(wp + 2),
              w3 = __ldg(wp + 3), w4 = __ldg(wp + 4);

        if (c < FDIM) {
            // raw features: gmem, coalesced per warp
            const float* src = xn + 24 * FDIM + c;
#pragma unroll
            for (int t = 0; t < WINDOW; t++) {
                float v = __ldg(src + t * FDIM);
#pragma unroll
                for (int k = 0; k < 5; k++) {
                    int l = t - k;
                    if (l >= 0 && l < LOUT) {
                        float wk = (k == 0) ? w0 : (k == 1) ? w1 : (k == 2) ? w2 : (k == 3) ? w3 : w4;
                        acc[l] += v * wk;
                    }
                }
            }
        } else {
            // derived features: all smem, uniform pointer+stride
            int cc = c - FDIM;
            int grp = (cc >= 40) ? 1 : 0;
            int r = cc - grp * 40;
            int se = r >> 3;                  // 0 mean,1 std,2 rank,3 max,4 min
            int ee = r & 7;
            const float* s_src;
            int s_stride;
            if (se == 2) {
                s_src = rank_row + ee;        // identical for week/month
                s_stride = 8;
            } else {
                int statid = (se < 2 ? se : se - 1) + grp * 4;
                s_src = stats + statid * 8 + ee;
                s_stride = 64;
            }
#pragma unroll
            for (int t = 0; t < WINDOW; t++) {
                float v = s_src[t * s_stride];
#pragma unroll
                for (int k = 0; k < 5; k++) {
                    int l = t - k;
                    if (l >= 0 && l < LOUT) {
                        float wk = (k == 0) ? w0 : (k == 1) ? w1 : (k == 2) ? w2 : (k == 3) ? w3 : w4;
                        acc[l] += v * wk;
                    }
                }
            }
        }
    }

    // reduce across the 5 channel-owning warps
    if (tid < 160) {
#pragma unroll
        for (int l = 0; l < LOUT; l++) {
            float a = acc[l];
#pragma unroll
            for (int o = 16; o > 0; o >>= 1)
                a += __shfl_xor_sync(0xFFFFFFFFu, a, o);
            if ((tid & 31) == 0) partial[tid >> 5][l] = a;
        }
    }
    __syncthreads();

    if (tid < LOUT) {
        float s = partial[0][tid] + partial[1][tid] + partial[2][tid] +
                  partial[3][tid] + partial[4][tid] + __ldg(conv_b + 127);
        float h = (s >= 0.f) ? s : 0.01f * s;
        fin[tid] = h * __ldg(lin_w + tid);
    }
    __syncthreads();

    if (tid == 0) {
        float s = __ldg(lin_b);
        for (int l = 0; l < LOUT; l++) s += fin[l];
        out[n] = s;
    }
}

// ---------------------------------------------------------------------------
extern "C" void kernel_launch(void* const* d_in, const int* in_sizes, int n_in,
                              void* d_out, int out_size) {
    const float* x      = (const float*)d_in[0];
    const float* conv_w = (const float*)d_in[1];
    const float* conv_b = (const float*)d_in[2];
    const float* lin_w  = (const float*)d_in[3];
    const float* lin_b  = (const float*)d_in[4];
    float* out = (float*)d_out;

    cudaFuncSetAttribute(rank_kernel, cudaFuncAttributeMaxDynamicSharedMemorySize, SMEM_A);

    rank_kernel<<<WINDOW * EE, RT, SMEM_A>>>(x);
    transpose_kernel<<<dim3((WINDOW * EE) / 32, NSTOCK / 32), dim3(32, 32)>>>();
    main_kernel<<<NSTOCK, 256>>>(x, conv_w, conv_b, lin_w, lin_b, out);
}

// round 4
// speedup vs baseline: 1.1779x; 1.1779x over previous
#include <cuda_runtime.h>
#include <cstdint>

#define WINDOW 40
#define EE 8
#define NSTOCK 8000
#define TDIM 64
#define FDIM 64
#define INCH 144
#define LOUT 36

// rank results, row-major [n][col], col = tw*8 + e
__device__ float g_rank_t[NSTOCK * WINDOW * EE];

// ---------------------------------------------------------------------------
// Kernel A: exact descending rank (stable, tie-break by index) per column.
// NB=16384 bins; u32 pack = (low-18 key bits << 13) | (8191 - n).
// smem: hist 65536 B + pack 32000 B = 97536 B -> 2 CTAs/SM.
// ---------------------------------------------------------------------------
#define NB 16384
#define RT 1024
#define SMEM_A (NB * 4 + NSTOCK * 4)

__global__ void __launch_bounds__(RT, 2) rank_kernel(const float* __restrict__ x) {
    extern __shared__ unsigned char smem_raw[];
    unsigned int* hist = (unsigned int*)smem_raw;              // NB u32 (counts -> offsets -> ends)
    unsigned int* pack = (unsigned int*)(smem_raw + NB * 4);   // NSTOCK u32

    __shared__ unsigned int wsum[32];

    const int col = blockIdx.x;
    const int tw  = col >> 3;
    const int e   = col & 7;
    const int tid = threadIdx.x;

    for (int i = tid; i < NB; i += RT) hist[i] = 0u;
    __syncthreads();

    const float* base = x + (24 + tw) * FDIM + e;

    // pass 1: keys -> registers, histogram on top 14 bits
    unsigned int rk[8];
#pragma unroll
    for (int i = 0; i < 8; i++) {
        int n = tid + i * RT;
        if (n < NSTOCK) {
            unsigned int u = __float_as_uint(__ldg(base + (size_t)n * (TDIM * FDIM)));
            u = (u & 0x80000000u) ? ~u : (u | 0x80000000u);
            rk[i] = u;
            atomicAdd(&hist[u >> 18], 1u);
        }
    }
    __syncthreads();

    // in-place exclusive prefix over NB bins (16 bins/thread)
    {
        const int CH = NB / RT;              // 16
        const int b0 = tid * CH;
        unsigned int s = 0;
#pragma unroll
        for (int j = 0; j < CH; j++) s += hist[b0 + j];

        const unsigned int lane = tid & 31u;
        const unsigned int wid  = tid >> 5;
        unsigned int v = s;
#pragma unroll
        for (int o = 1; o < 32; o <<= 1) {
            unsigned int t = __shfl_up_sync(0xFFFFFFFFu, v, o);
            if (lane >= (unsigned)o) v += t;
        }
        if (lane == 31u) wsum[wid] = v;
        __syncthreads();
        if (wid == 0) {
            unsigned int orig = wsum[lane];
            unsigned int w = orig;
#pragma unroll
            for (int o = 1; o < 32; o <<= 1) {
                unsigned int t = __shfl_up_sync(0xFFFFFFFFu, w, o);
                if (lane >= (unsigned)o) w += t;
            }
            wsum[lane] = w - orig;
        }
        __syncthreads();
        unsigned int run = wsum[wid] + (v - s);
#pragma unroll
        for (int j = 0; j < CH; j++) {
            unsigned int h = hist[b0 + j];
            hist[b0 + j] = run;
            run += h;
        }
    }
    __syncthreads();

    // pass 2: scatter u32 packs grouped by bin
#pragma unroll
    for (int i = 0; i < 8; i++) {
        int n = tid + i * RT;
        if (n < NSTOCK) {
            unsigned int u = rk[i];
            unsigned int p = atomicAdd(&hist[u >> 18], 1u);
            pack[p] = ((u & 0x3FFFFu) << 13) | (unsigned int)(8191 - n);
        }
    }
    __syncthreads();
    // hist[b] == end of bin b; start(b) = hist[b-1]

    // pass 3: greater-count over own bin segment; write rank straight to gmem
#pragma unroll
    for (int i = 0; i < 8; i++) {
        int n = tid + i * RT;
        if (n < NSTOCK) {
            unsigned int u = rk[i];
            unsigned int b = u >> 18;
            unsigned int end = hist[b];
            unsigned int start = b ? hist[b - 1] : 0u;
            unsigned int pk = ((u & 0x3FFFFu) << 13) | (unsigned int)(8191 - n);
            unsigned int g = (unsigned int)NSTOCK - end;
            for (unsigned int q = start; q < end; q++)
                g += (pack[q] > pk) ? 1u : 0u;
            g_rank_t[(size_t)n * (WINDOW * EE) + col] = (float)g * (1.0f / (float)NSTOCK);
        }
    }
}

// ---------------------------------------------------------------------------
// Kernel B: fused stats + conv (only out-channel 127 matters) + linear.
// 320 threads: conv split into two 18-output halves (acc[18] per thread).
// ---------------------------------------------------------------------------
__global__ void __launch_bounds__(320) main_kernel(
    const float* __restrict__ x,
    const float* __restrict__ conv_w,
    const float* __restrict__ conv_b,
    const float* __restrict__ lin_w,
    const float* __restrict__ lin_b,
    float* __restrict__ out)
{
    __shared__ __align__(16) float xe[59][9];             // x[n, 5:64, 0:8]
    __shared__ __align__(16) float stats[WINDOW * 64];    // [tw][statid*8 + e]
    __shared__ __align__(16) float rank_row[WINDOW * EE];
    __shared__ float partial[10][18];
    __shared__ float fin[LOUT];

    const int n = blockIdx.x;
    const int tid = threadIdx.x;
    const float* xn = x + (size_t)n * (TDIM * FDIM);

    // load xe = x[n, 5:64, 0:8]
    for (int i = tid; i < 59 * 8; i += 320) {
        int tt = i >> 3, ee = i & 7;
        xe[tt][ee] = __ldg(xn + (5 + tt) * FDIM + ee);
    }
    // load rank row (contiguous float4; gmem base 256B-aligned, row stride 1280B)
    if (tid < (WINDOW * EE) / 4) {
        const float4* rsrc = (const float4*)(g_rank_t + (size_t)n * (WINDOW * EE));
        ((float4*)rank_row)[tid] = rsrc[tid];
    }
    __syncthreads();

    // stats: exactly one (tw, e) task per thread
    {
        int tw = tid >> 3, ee = tid & 7;
        int te = 19 + tw;

        float s5 = 0.f, mx5 = -1e30f, mn5 = 1e30f;
#pragma unroll
        for (int j = 0; j < 5; j++) {
            float v = xe[te - 4 + j][ee];
            s5 += v; mx5 = fmaxf(mx5, v); mn5 = fminf(mn5, v);
        }
        float m5 = s5 * 0.2f;
        float var5 = 0.f;
#pragma unroll
        for (int j = 0; j < 5; j++) {
            float d = xe[te - 4 + j][ee] - m5;
            var5 += d * d;
        }
        float sd5 = sqrtf(var5 * 0.25f);

        float s20 = 0.f, mx20 = -1e30f, mn20 = 1e30f;
#pragma unroll
        for (int j = 0; j < 20; j++) {
            float v = xe[te - 19 + j][ee];
            s20 += v; mx20 = fmaxf(mx20, v); mn20 = fminf(mn20, v);
        }
        float m20 = s20 * 0.05f;
        float var20 = 0.f;
#pragma unroll
        for (int j = 0; j < 20; j++) {
            float d = xe[te - 19 + j][ee] - m20;
            var20 += d * d;
        }
        float sd20 = sqrtf(var20 * (1.0f / 19.0f));

        float* st = stats + tw * 64 + ee;
        st[0]  = m5;   st[8]  = sd5;  st[16] = mx5;  st[24] = mn5;
        st[32] = m20;  st[40] = sd20; st[48] = mx20; st[56] = mn20;
    }
    __syncthreads();

    // conv: two threads per channel, each covering 18 of the 36 outputs
    float acc[18];
#pragma unroll
    for (int j = 0; j < 18; j++) acc[j] = 0.f;

    const int hh = (tid >= 160) ? 1 : 0;
    const int c  = tid - hh * 160;
    const int l0 = hh * 18;

    if (c < INCH) {
        const float* wp = conv_w + 127 * (INCH * 5) + c * 5;
        float w0 = __ldg(wp + 0), w1 = __ldg(wp + 1), w2 = __ldg(wp + 2),
              w3 = __ldg(wp + 3), w4 = __ldg(wp + 4);

        if (c < FDIM) {
            const float* src = xn + (24 + l0) * FDIM + c;
#pragma unroll
            for (int tt = 0; tt < 22; tt++) {        // t = l0 + tt, t - l0 = tt
                float v = __ldg(src + tt * FDIM);
#pragma unroll
                for (int k = 0; k < 5; k++) {
                    int j = tt - k;                   // l - l0
                    if (j >= 0 && j < 18) {
                        float wk = (k == 0) ? w0 : (k == 1) ? w1 : (k == 2) ? w2 : (k == 3) ? w3 : w4;
                        acc[j] += v * wk;
                    }
                }
            }
        } else {
            int cc = c - FDIM;
            int grp = (cc >= 40) ? 1 : 0;
            int r = cc - grp * 40;
            int se = r >> 3;                  // 0 mean,1 std,2 rank,3 max,4 min
            int ee = r & 7;
            const float* s_src;
            int s_stride;
            if (se == 2) {
                s_src = rank_row + ee;        // identical for week/month
                s_stride = 8;
            } else {
                int statid = (se < 2 ? se : se - 1) + grp * 4;
                s_src = stats + statid * 8 + ee;
                s_stride = 64;
            }
            s_src += l0 * s_stride;
#pragma unroll
            for (int tt = 0; tt < 22; tt++) {
                float v = s_src[tt * s_stride];
#pragma unroll
                for (int k = 0; k < 5; k++) {
                    int j = tt - k;
                    if (j >= 0 && j < 18) {
                        float wk = (k == 0) ? w0 : (k == 1) ? w1 : (k == 2) ? w2 : (k == 3) ? w3 : w4;
                        acc[j] += v * wk;
                    }
                }
            }
        }
    }

    // warp reduction: warp w holds 32 channels of one half
    {
        const int w = tid >> 5;   // 0..9
#pragma unroll
        for (int j = 0; j < 18; j++) {
            float a = acc[j];
#pragma unroll
            for (int o = 16; o > 0; o >>= 1)
                a += __shfl_xor_sync(0xFFFFFFFFu, a, o);
            if ((tid & 31) == 0) partial[w][j] = a;
        }
    }
    __syncthreads();

    if (tid < LOUT) {
        int h2 = (tid >= 18) ? 1 : 0;
        int j = tid - h2 * 18;
        int wb = h2 * 5;
        float s = partial[wb][j] + partial[wb + 1][j] + partial[wb + 2][j] +
                  partial[wb + 3][j] + partial[wb + 4][j] + __ldg(conv_b + 127);
        float hv = (s >= 0.f) ? s : 0.01f * s;
        fin[tid] = hv * __ldg(lin_w + tid);
    }
    __syncthreads();

    if (tid == 0) {
        float s = __ldg(lin_b);
        for (int l = 0; l < LOUT; l++) s += fin[l];
        out[n] = s;
    }
}

// ---------------------------------------------------------------------------
extern "C" void kernel_launch(void* const* d_in, const int* in_sizes, int n_in,
                              void* d_out, int out_size) {
    const float* x      = (const float*)d_in[0];
    const float* conv_w = (const float*)d_in[1];
    const float* conv_b = (const float*)d_in[2];
    const float* lin_w  = (const float*)d_in[3];
    const float* lin_b  = (const float*)d_in[4];
    float* out = (float*)d_out;

    cudaFuncSetAttribute(rank_kernel, cudaFuncAttributeMaxDynamicSharedMemorySize, SMEM_A);

    rank_kernel<<<WINDOW * EE, RT, SMEM_A>>>(x);
    main_kernel<<<NSTOCK, 320>>>(x, conv_w, conv_b, lin_w, lin_b, out);
}

// round 5
// speedup vs baseline: 1.4732x; 1.2507x over previous
#include <cuda_runtime.h>
#include <cstdint>

#define WINDOW 40
#define EE 8
#define NSTOCK 8000
#define TDIM 64
#define FDIM 64
#define INCH 144
#define LOUT 36

// rank results, row-major [n][col], col = tw*8 + e
__device__ float g_rank_t[NSTOCK * WINDOW * EE];

// ---------------------------------------------------------------------------
// Kernel A: exact descending rank via two-level equidistributing counting.
// 512 threads, 2 CTAs/SM. smem: h1p (16384 u16 bins packed, +sentinel) 32.8KB
//                               h2p (8192 u16 bins packed) 16.4KB
//                               pack (8000 u32) 32KB          total 81184 B
// ---------------------------------------------------------------------------
#define RT 512
#define H1W 8200                      // words for level-1 (8192 + sentinel + pad)
#define H2W 4096                      // words for level-2 (8192 bins)
#define SMEM_R (H1W * 4 + H2W * 4 + (NSTOCK + 8) * 4)

__global__ void __launch_bounds__(RT, 2) rank_kernel(const float* __restrict__ x) {
    extern __shared__ unsigned char smem_raw[];
    unsigned int* h1p  = (unsigned int*)smem_raw;                         // packed u16 pairs
    unsigned int* h2p  = (unsigned int*)(smem_raw + H1W * 4);             // packed u16 pairs
    unsigned int* pack = (unsigned int*)(smem_raw + H1W * 4 + H2W * 4);   // u32 keys

    __shared__ unsigned int wsum[16];

    const int col = blockIdx.x;
    const int tw  = col >> 3;
    const int e   = col & 7;
    const int tid = threadIdx.x;
    const unsigned int lane = tid & 31u;
    const unsigned int wid  = tid >> 5;

    // zero both histograms
    for (int i = tid; i < H1W; i += RT) h1p[i] = 0u;
    for (int i = tid; i < H2W; i += RT) h2p[i] = 0u;
    __syncthreads();

    const float* basep = x + (24 + tw) * FDIM + e;

    // ---- P1: load keys (kept in regs), level-1 histogram on top 14 bits ----
    unsigned int rk[16];
#pragma unroll
    for (int i = 0; i < 16; i++) {
        int n = tid + (i << 9);
        if (n < NSTOCK) {
            unsigned int u = __float_as_uint(__ldg(basep + (size_t)n * (TDIM * FDIM)));
            u = (u & 0x80000000u) ? ~u : (u | 0x80000000u);
            rk[i] = u;
            unsigned int b = u >> 18;
            atomicAdd(&h1p[b >> 1], (b & 1u) ? 65536u : 1u);
        }
    }
    __syncthreads();

    // ---- level-1 exclusive prefix over 16384 bins (16 words / thread) ----
    {
        const int W0 = tid * 16;
        unsigned int s = 0;
#pragma unroll
        for (int j = 0; j < 16; j++) {
            unsigned int w = h1p[W0 + j];
            s += (w & 0xFFFFu) + (w >> 16);
        }
        unsigned int v = s;
#pragma unroll
        for (int o = 1; o < 32; o <<= 1) {
            unsigned int t = __shfl_up_sync(0xFFFFFFFFu, v, o);
            if (lane >= (unsigned)o) v += t;
        }
        if (lane == 31u) wsum[wid] = v;
        __syncthreads();
        if (wid == 0) {
            unsigned int orig = (lane < 16u) ? wsum[lane] : 0u;
            unsigned int w = orig;
#pragma unroll
            for (int o = 1; o < 32; o <<= 1) {
                unsigned int t = __shfl_up_sync(0xFFFFFFFFu, w, o);
                if (lane >= (unsigned)o) w += t;
            }
            if (lane < 16u) wsum[lane] = w - orig;
        }
        __syncthreads();
        unsigned int run = wsum[wid] + (v - s);
#pragma unroll
        for (int j = 0; j < 16; j++) {
            unsigned int w = h1p[W0 + j];
            unsigned int lo = w & 0xFFFFu, hi = w >> 16;
            h1p[W0 + j] = run | ((run + lo) << 16);
            run += lo + hi;
        }
        if (tid == 0) h1p[8192] = (unsigned int)NSTOCK;  // sentinel S[16384]
    }
    __syncthreads();

    // ---- P2: compute level-2 bin per element + level-2 histogram ----
    unsigned int lvp[8];   // 16 x u16 packed
#pragma unroll
    for (int i = 0; i < 16; i++) {
        int n = tid + (i << 9);
        unsigned int l2 = 0u;
        if (n < NSTOCK) {
            unsigned int u = rk[i];
            unsigned int b = u >> 18;
            unsigned int w = h1p[b >> 1];
            unsigned int s0, s1;
            if (b & 1u) { s0 = w >> 16; s1 = h1p[(b >> 1) + 1] & 0xFFFFu; }
            else        { s0 = w & 0xFFFFu; s1 = w >> 16; }
            unsigned int c = s1 - s0;
            unsigned int sub = ((u & 0x3FFFFu) * c) >> 18;
            l2 = s0 + sub;
            atomicAdd(&h2p[l2 >> 1], (l2 & 1u) ? 65536u : 1u);
        }
        if (i & 1) lvp[i >> 1] |= (l2 << 16);
        else       lvp[i >> 1]  = l2;
    }
    __syncthreads();

    // ---- level-2 exclusive prefix over 8192 bins (8 words / thread) ----
    {
        const int W0 = tid * 8;
        unsigned int s = 0;
#pragma unroll
        for (int j = 0; j < 8; j++) {
            unsigned int w = h2p[W0 + j];
            s += (w & 0xFFFFu) + (w >> 16);
        }
        unsigned int v = s;
#pragma unroll
        for (int o = 1; o < 32; o <<= 1) {
            unsigned int t = __shfl_up_sync(0xFFFFFFFFu, v, o);
            if (lane >= (unsigned)o) v += t;
        }
        if (lane == 31u) wsum[wid] = v;
        __syncthreads();
        if (wid == 0) {
            unsigned int orig = (lane < 16u) ? wsum[lane] : 0u;
            unsigned int w = orig;
#pragma unroll
            for (int o = 1; o < 32; o <<= 1) {
                unsigned int t = __shfl_up_sync(0xFFFFFFFFu, w, o);
                if (lane >= (unsigned)o) w += t;
            }
            if (lane < 16u) wsum[lane] = w - orig;
        }
        __syncthreads();
        unsigned int run = wsum[wid] + (v - s);
#pragma unroll
        for (int j = 0; j < 8; j++) {
            unsigned int w = h2p[W0 + j];
            unsigned int lo = w & 0xFFFFu, hi = w >> 16;
            h2p[W0 + j] = run | ((run + lo) << 16);
            run += lo + hi;
        }
    }
    __syncthreads();

    // ---- P3: scatter 31-bit tie-break keys grouped by level-2 bin ----
#pragma unroll
    for (int i = 0; i < 16; i++) {
        int n = tid + (i << 9);
        if (n < NSTOCK) {
            unsigned int u = rk[i];
            unsigned int l2 = (i & 1) ? (lvp[i >> 1] >> 16) : (lvp[i >> 1] & 0xFFFFu);
            unsigned int old = atomicAdd(&h2p[l2 >> 1], (l2 & 1u) ? 65536u : 1u);
            unsigned int pos = (old >> ((l2 & 1u) * 16u)) & 0xFFFFu;
            pack[pos] = ((u & 0x3FFFFu) << 13) | (8191u - (unsigned)n);
        }
    }
    __syncthreads();
    // h2p[bin] (packed halves) now holds END offsets.

    // ---- P4: rank = (count above segment) + (in-segment strictly-greater) ----
#pragma unroll
    for (int i = 0; i < 16; i++) {
        int n = tid + (i << 9);
        if (n < NSTOCK) {
            unsigned int u = rk[i];
            unsigned int l2 = (i & 1) ? (lvp[i >> 1] >> 16) : (lvp[i >> 1] & 0xFFFFu);
            unsigned int wE = h2p[l2 >> 1];
            unsigned int end = (wE >> ((l2 & 1u) * 16u)) & 0xFFFFu;
            unsigned int start = 0u;
            if (l2 != 0u) {
                unsigned int j = l2 - 1u;
                unsigned int wS = ((j >> 1) == (l2 >> 1)) ? wE : h2p[j >> 1];
                start = (wS >> ((j & 1u) * 16u)) & 0xFFFFu;
            }
            unsigned int K = ((u & 0x3FFFFu) << 13) | (8191u - (unsigned)n);
            unsigned int g = (unsigned int)NSTOCK - end;
            for (unsigned int q = start; q < end; q++)
                g += (pack[q] > K) ? 1u : 0u;
            g_rank_t[(size_t)n * (WINDOW * EE) + col] = (float)g * (1.0f / (float)NSTOCK);
        }
    }
}

// ---------------------------------------------------------------------------
// Kernel B: fused stats (prefix-sum based) + conv (out-channel 127) + linear
// ---------------------------------------------------------------------------
__global__ void __launch_bounds__(320) main_kernel(
    const float* __restrict__ x,
    const float* __restrict__ conv_w,
    const float* __restrict__ conv_b,
    const float* __restrict__ lin_w,
    const float* __restrict__ lin_b,
    float* __restrict__ out)
{
    __shared__ __align__(16) float xe[59][9];             // x[n, 5:64, 0:8]
    __shared__ __align__(16) float Pp[60][8];             // prefix sum per ee
    __shared__ __align__(16) float Qq[60][8];             // prefix sum of squares
    __shared__ __align__(16) float stats[WINDOW * 64];    // [tw][statid*8 + e]
    __shared__ __align__(16) float rank_row[WINDOW * EE];
    __shared__ float partial[10][18];
    __shared__ float fin[LOUT];

    const int n = blockIdx.x;
    const int tid = threadIdx.x;
    const float* xn = x + (size_t)n * (TDIM * FDIM);

    // load xe = x[n, 5:64, 0:8]
    for (int i = tid; i < 59 * 8; i += 320) {
        int tt = i >> 3, ee = i & 7;
        xe[tt][ee] = __ldg(xn + (5 + tt) * FDIM + ee);
    }
    // load rank row (contiguous float4)
    if (tid < (WINDOW * EE) / 4) {
        const float4* rsrc = (const float4*)(g_rank_t + (size_t)n * (WINDOW * EE));
        ((float4*)rank_row)[tid] = rsrc[tid];
    }
    __syncthreads();

    // per-ee prefix sums (8 threads serial; others wait)
    if (tid < 8) {
        float run = 0.f, runq = 0.f;
#pragma unroll 1
        for (int r = 0; r < 59; r++) {
            float v = xe[r][tid];
            Pp[r][tid] = run; Qq[r][tid] = runq;
            run += v; runq = fmaf(v, v, runq);
        }
        Pp[59][tid] = run; Qq[59][tid] = runq;
    }
    __syncthreads();

    // stats: one (tw, ee) task per thread
    {
        int tw = tid >> 3, ee = tid & 7;
        int te = 19 + tw;

        float pt = Pp[te + 1][ee], qt = Qq[te + 1][ee];
        float sum20 = pt - Pp[te - 19][ee];
        float q20   = qt - Qq[te - 19][ee];
        float m20   = sum20 * 0.05f;
        float sd20  = sqrtf(fmaxf(fmaf(-sum20, m20, q20) * (1.0f / 19.0f), 0.f));

        float sum5 = pt - Pp[te - 4][ee];
        float q5   = qt - Qq[te - 4][ee];
        float m5   = sum5 * 0.2f;
        float sd5  = sqrtf(fmaxf(fmaf(-sum5, m5, q5) * 0.25f, 0.f));

        float mx20 = -1e30f, mn20 = 1e30f, mx5 = -1e30f, mn5 = 1e30f;
#pragma unroll
        for (int j = 0; j < 20; j++) {
            float v = xe[te - 19 + j][ee];
            mx20 = fmaxf(mx20, v); mn20 = fminf(mn20, v);
            if (j >= 15) { mx5 = fmaxf(mx5, v); mn5 = fminf(mn5, v); }
        }

        float* st = stats + tw * 64 + ee;
        st[0]  = m5;   st[8]  = sd5;  st[16] = mx5;  st[24] = mn5;
        st[32] = m20;  st[40] = sd20; st[48] = mx20; st[56] = mn20;
    }
    __syncthreads();

    // conv: two threads per channel, each covering 18 of the 36 outputs
    float acc[18];
#pragma unroll
    for (int j = 0; j < 18; j++) acc[j] = 0.f;

    const int hh = (tid >= 160) ? 1 : 0;
    const int c  = tid - hh * 160;
    const int l0 = hh * 18;

    if (c < INCH) {
        const float* wp = conv_w + 127 * (INCH * 5) + c * 5;
        float w0 = __ldg(wp + 0), w1 = __ldg(wp + 1), w2 = __ldg(wp + 2),
              w3 = __ldg(wp + 3), w4 = __ldg(wp + 4);

        if (c < FDIM) {
            const float* src = xn + (24 + l0) * FDIM + c;
#pragma unroll
            for (int tt = 0; tt < 22; tt++) {
                float v = __ldg(src + tt * FDIM);
#pragma unroll
                for (int k = 0; k < 5; k++) {
                    int j = tt - k;
                    if (j >= 0 && j < 18) {
                        float wk = (k == 0) ? w0 : (k == 1) ? w1 : (k == 2) ? w2 : (k == 3) ? w3 : w4;
                        acc[j] += v * wk;
                    }
                }
            }
        } else {
            int cc = c - FDIM;
            int grp = (cc >= 40) ? 1 : 0;
            int r = cc - grp * 40;
            int se = r >> 3;                  // 0 mean,1 std,2 rank,3 max,4 min
            int ee = r & 7;
            const float* s_src;
            int s_stride;
            if (se == 2) {
                s_src = rank_row + ee;        // identical for week/month
                s_stride = 8;
            } else {
                int statid = (se < 2 ? se : se - 1) + grp * 4;
                s_src = stats + statid * 8 + ee;
                s_stride = 64;
            }
            s_src += l0 * s_stride;
#pragma unroll
            for (int tt = 0; tt < 22; tt++) {
                float v = s_src[tt * s_stride];
#pragma unroll
                for (int k = 0; k < 5; k++) {
                    int j = tt - k;
                    if (j >= 0 && j < 18) {
                        float wk = (k == 0) ? w0 : (k == 1) ? w1 : (k == 2) ? w2 : (k == 3) ? w3 : w4;
                        acc[j] += v * wk;
                    }
                }
            }
        }
    }

    // warp reduction
    {
        const int w = tid >> 5;
#pragma unroll
        for (int j = 0; j < 18; j++) {
            float a = acc[j];
#pragma unroll
            for (int o = 16; o > 0; o >>= 1)
                a += __shfl_xor_sync(0xFFFFFFFFu, a, o);
            if ((tid & 31) == 0) partial[w][j] = a;
        }
    }
    __syncthreads();

    if (tid < LOUT) {
        int h2 = (tid >= 18) ? 1 : 0;
        int j = tid - h2 * 18;
        int wb = h2 * 5;
        float s = partial[wb][j] + partial[wb + 1][j] + partial[wb + 2][j] +
                  partial[wb + 3][j] + partial[wb + 4][j] + __ldg(conv_b + 127);
        float hv = (s >= 0.f) ? s : 0.01f * s;
        fin[tid] = hv * __ldg(lin_w + tid);
    }
    __syncthreads();

    if (tid == 0) {
        float s = __ldg(lin_b);
        for (int l = 0; l < LOUT; l++) s += fin[l];
        out[n] = s;
    }
}

// ---------------------------------------------------------------------------
extern "C" void kernel_launch(void* const* d_in, const int* in_sizes, int n_in,
                              void* d_out, int out_size) {
    const float* x      = (const float*)d_in[0];
    const float* conv_w = (const float*)d_in[1];
    const float* conv_b = (const float*)d_in[2];
    const float* lin_w  = (const float*)d_in[3];
    const float* lin_b  = (const float*)d_in[4];
    float* out = (float*)d_out;

    cudaFuncSetAttribute(rank_kernel, cudaFuncAttributeMaxDynamicSharedMemorySize, SMEM_R);

    rank_kernel<<<WINDOW * EE, RT, SMEM_R>>>(x);
    main_kernel<<<NSTOCK, 320>>>(x, conv_w, conv_b, lin_w, lin_b, out);
}

// round 7
// speedup vs baseline: 1.6327x; 1.1082x over previous
#include <cuda_runtime.h>
#include <cstdint>

#define WINDOW 40
#define EE 8
#define NSTOCK 8000
#define TDIM 64
#define FDIM 64
#define INCH 144
#define LOUT 36

__device__ float g_rank[WINDOW * EE * NSTOCK];      // [col][n]  (coalesced writes)
__device__ float g_rank_t[NSTOCK * WINDOW * EE];    // [n][col]  (coalesced reads in main)

// ---------------------------------------------------------------------------
// Kernel A: exact descending rank via two-level equidistributing counting.
// 512 threads, 2 CTAs/SM. smem = 81184 B.
// ---------------------------------------------------------------------------
#define RT 512
#define H1W 8200
#define H2W 4096
#define SMEM_R (H1W * 4 + H2W * 4 + (NSTOCK + 8) * 4)

__global__ void __launch_bounds__(RT, 2) rank_kernel(const float* __restrict__ x) {
    extern __shared__ unsigned char smem_raw[];
    unsigned int* h1p  = (unsigned int*)smem_raw;
    unsigned int* h2p  = (unsigned int*)(smem_raw + H1W * 4);
    unsigned int* pack = (unsigned int*)(smem_raw + H1W * 4 + H2W * 4);

    __shared__ unsigned int wsum[16];

    const int col = blockIdx.x;
    const int tw  = col >> 3;
    const int e   = col & 7;
    const int tid = threadIdx.x;
    const unsigned int lane = tid & 31u;
    const unsigned int wid  = tid >> 5;

    for (int i = tid; i < H1W; i += RT) h1p[i] = 0u;
    for (int i = tid; i < H2W; i += RT) h2p[i] = 0u;
    __syncthreads();

    const float* basep = x + (24 + tw) * FDIM + e;

    // P1: keys -> regs, level-1 histogram (top 14 bits), packed u16 counters
    unsigned int rk[16];
#pragma unroll
    for (int i = 0; i < 16; i++) {
        int n = tid + (i << 9);
        if (n < NSTOCK) {
            unsigned int u = __float_as_uint(__ldg(basep + (size_t)n * (TDIM * FDIM)));
            u = (u & 0x80000000u) ? ~u : (u | 0x80000000u);
            rk[i] = u;
            unsigned int b = u >> 18;
            atomicAdd(&h1p[b >> 1], (b & 1u) ? 65536u : 1u);
        }
    }
    __syncthreads();

    // level-1 exclusive prefix (16 words / thread)
    {
        const int W0 = tid * 16;
        unsigned int s = 0;
#pragma unroll
        for (int j = 0; j < 16; j++) {
            unsigned int w = h1p[W0 + j];
            s += (w & 0xFFFFu) + (w >> 16);
        }
        unsigned int v = s;
#pragma unroll
        for (int o = 1; o < 32; o <<= 1) {
            unsigned int t = __shfl_up_sync(0xFFFFFFFFu, v, o);
            if (lane >= (unsigned)o) v += t;
        }
        if (lane == 31u) wsum[wid] = v;
        __syncthreads();
        if (wid == 0) {
            unsigned int orig = (lane < 16u) ? wsum[lane] : 0u;
            unsigned int w = orig;
#pragma unroll
            for (int o = 1; o < 32; o <<= 1) {
                unsigned int t = __shfl_up_sync(0xFFFFFFFFu, w, o);
                if (lane >= (unsigned)o) w += t;
            }
            if (lane < 16u) wsum[lane] = w - orig;
        }
        __syncthreads();
        unsigned int run = wsum[wid] + (v - s);
#pragma unroll
        for (int j = 0; j < 16; j++) {
            unsigned int w = h1p[W0 + j];
            unsigned int lo = w & 0xFFFFu, hi = w >> 16;
            h1p[W0 + j] = run | ((run + lo) << 16);
            run += lo + hi;
        }
        if (tid == 0) h1p[8192] = (unsigned int)NSTOCK;
    }
    __syncthreads();

    // P2: level-2 bin per element + level-2 histogram
    unsigned int lvp[8];
#pragma unroll
    for (int i = 0; i < 16; i++) {
        int n = tid + (i << 9);
        unsigned int l2 = 0u;
        if (n < NSTOCK) {
            unsigned int u = rk[i];
            unsigned int b = u >> 18;
            unsigned int w = h1p[b >> 1];
            unsigned int s0, s1;
            if (b & 1u) { s0 = w >> 16; s1 = h1p[(b >> 1) + 1] & 0xFFFFu; }
            else        { s0 = w & 0xFFFFu; s1 = w >> 16; }
            unsigned int c = s1 - s0;
            unsigned int sub = ((u & 0x3FFFFu) * c) >> 18;
            l2 = s0 + sub;
            atomicAdd(&h2p[l2 >> 1], (l2 & 1u) ? 65536u : 1u);
        }
        if (i & 1) lvp[i >> 1] |= (l2 << 16);
        else       lvp[i >> 1]  = l2;
    }
    __syncthreads();

    // level-2 exclusive prefix (8 words / thread)
    {
        const int W0 = tid * 8;
        unsigned int s = 0;
#pragma unroll
        for (int j = 0; j < 8; j++) {
            unsigned int w = h2p[W0 + j];
            s += (w & 0xFFFFu) + (w >> 16);
        }
        unsigned int v = s;
#pragma unroll
        for (int o = 1; o < 32; o <<= 1) {
            unsigned int t = __shfl_up_sync(0xFFFFFFFFu, v, o);
            if (lane >= (unsigned)o) v += t;
        }
        if (lane == 31u) wsum[wid] = v;
        __syncthreads();
        if (wid == 0) {
            unsigned int orig = (lane < 16u) ? wsum[lane] : 0u;
            unsigned int w = orig;
#pragma unroll
            for (int o = 1; o < 32; o <<= 1) {
                unsigned int t = __shfl_up_sync(0xFFFFFFFFu, w, o);
                if (lane >= (unsigned)o) w += t;
            }
            if (lane < 16u) wsum[lane] = w - orig;
        }
        __syncthreads();
        unsigned int run = wsum[wid] + (v - s);
#pragma unroll
        for (int j = 0; j < 8; j++) {
            unsigned int w = h2p[W0 + j];
            unsigned int lo = w & 0xFFFFu, hi = w >> 16;
            h2p[W0 + j] = run | ((run + lo) << 16);
            run += lo + hi;
        }
    }
    __syncthreads();

    // P3: scatter 31-bit tie-break keys grouped by level-2 bin
#pragma unroll
    for (int i = 0; i < 16; i++) {
        int n = tid + (i << 9);
        if (n < NSTOCK) {
            unsigned int u = rk[i];
            unsigned int l2 = (i & 1) ? (lvp[i >> 1] >> 16) : (lvp[i >> 1] & 0xFFFFu);
            unsigned int old = atomicAdd(&h2p[l2 >> 1], (l2 & 1u) ? 65536u : 1u);
            unsigned int pos = (old >> ((l2 & 1u) * 16u)) & 0xFFFFu;
            pack[pos] = ((u & 0x3FFFFu) << 13) | (8191u - (unsigned)n);
        }
    }
    __syncthreads();

    // P4: rank = above-segment count + in-segment strictly-greater; COALESCED store
    float* dst = g_rank + (size_t)col * NSTOCK;
#pragma unroll
    for (int i = 0; i < 16; i++) {
        int n = tid + (i << 9);
        if (n < NSTOCK) {
            unsigned int u = rk[i];
            unsigned int l2 = (i & 1) ? (lvp[i >> 1] >> 16) : (lvp[i >> 1] & 0xFFFFu);
            unsigned int wE = h2p[l2 >> 1];
            unsigned int end = (wE >> ((l2 & 1u) * 16u)) & 0xFFFFu;
            unsigned int start = 0u;
            if (l2 != 0u) {
                unsigned int j = l2 - 1u;
                unsigned int wS = ((j >> 1) == (l2 >> 1)) ? wE : h2p[j >> 1];
                start = (wS >> ((j & 1u) * 16u)) & 0xFFFFu;
            }
            unsigned int K = ((u & 0x3FFFFu) << 13) | (8191u - (unsigned)n);
            unsigned int g = (unsigned int)NSTOCK - end;
            for (unsigned int q = start; q < end; q++)
                g += (pack[q] > K) ? 1u : 0u;
            dst[n] = (float)g * (1.0f / (float)NSTOCK);
        }
    }
}

// ---------------------------------------------------------------------------
// Transpose [col][n] -> [n][col]
// ---------------------------------------------------------------------------
__global__ void transpose_kernel() {
    __shared__ float tile[32][33];
    const int c0 = blockIdx.x * 32;
    const int n0 = blockIdx.y * 32;
    const int tx = threadIdx.x, ty = threadIdx.y;
    tile[ty][tx] = g_rank[(size_t)(c0 + ty) * NSTOCK + n0 + tx];
    __syncthreads();
    g_rank_t[(size_t)(n0 + ty) * (WINDOW * EE) + c0 + tx] = tile[tx][ty];
}

// ---------------------------------------------------------------------------
// Kernel B: fused stats (direct two-pass) + conv (out-channel 127) + linear
// ---------------------------------------------------------------------------
__global__ void __launch_bounds__(320) main_kernel(
    const float* __restrict__ x,
    const float* __restrict__ conv_w,
    const float* __restrict__ conv_b,
    const float* __restrict__ lin_w,
    const float* __restrict__ lin_b,
    float* __restrict__ out)
{
    __shared__ __align__(16) float xe[59][9];
    __shared__ __align__(16) float stats[WINDOW * 64];
    __shared__ __align__(16) float rank_row[WINDOW * EE];
    __shared__ float partial[10][18];
    __shared__ float fin[LOUT];

    const int n = blockIdx.x;
    const int tid = threadIdx.x;
    const float* xn = x + (size_t)n * (TDIM * FDIM);

    for (int i = tid; i < 59 * 8; i += 320) {
        int tt = i >> 3, ee = i & 7;
        xe[tt][ee] = __ldg(xn + (5 + tt) * FDIM + ee);
    }
    if (tid < (WINDOW * EE) / 4) {
        const float4* rsrc = (const float4*)(g_rank_t + (size_t)n * (WINDOW * EE));
        ((float4*)rank_row)[tid] = rsrc[tid];
    }
    __syncthreads();

    // stats: one (tw, ee) task per thread, direct two-pass, folded max/min
    {
        int tw = tid >> 3, ee = tid & 7;
        int te = 19 + tw;

        float s20 = 0.f, mx20 = -1e30f, mn20 = 1e30f;
        float s5 = 0.f, mx5 = -1e30f, mn5 = 1e30f;
#pragma unroll
        for (int j = 0; j < 20; j++) {
            float v = xe[te - 19 + j][ee];
            s20 += v; mx20 = fmaxf(mx20, v); mn20 = fminf(mn20, v);
            if (j >= 15) { s5 += v; mx5 = fmaxf(mx5, v); mn5 = fminf(mn5, v); }
        }
        float m20 = s20 * 0.05f;
        float m5  = s5 * 0.2f;
        float var20 = 0.f, var5 = 0.f;
#pragma unroll
        for (int j = 0; j < 20; j++) {
            float v = xe[te - 19 + j][ee];
            float d20 = v - m20;
            var20 = fmaf(d20, d20, var20);
            if (j >= 15) { float d5 = v - m5; var5 = fmaf(d5, d5, var5); }
        }
        float sd20 = sqrtf(var20 * (1.0f / 19.0f));
        float sd5  = sqrtf(var5 * 0.25f);

        float* st = stats + tw * 64 + ee;
        st[0]  = m5;   st[8]  = sd5;  st[16] = mx5;  st[24] = mn5;
        st[32] = m20;  st[40] = sd20; st[48] = mx20; st[56] = mn20;
    }
    __syncthreads();

    // conv: two threads per channel, each covering 18 of 36 outputs
    float acc[18];
#pragma unroll
    for (int j = 0; j < 18; j++) acc[j] = 0.f;

    const int hh = (tid >= 160) ? 1 : 0;
    const int c  = tid - hh * 160;
    const int l0 = hh * 18;

    if (c < INCH) {
        const float* wp = conv_w + 127 * (INCH * 5) + c * 5;
        float w0 = __ldg(wp + 0), w1 = __ldg(wp + 1), w2 = __ldg(wp + 2),
              w3 = __ldg(wp + 3), w4 = __ldg(wp + 4);

        if (c < FDIM) {
            const float* src = xn + (24 + l0) * FDIM + c;
#pragma unroll
            for (int tt = 0; tt < 22; tt++) {
                float v = __ldg(src + tt * FDIM);
#pragma unroll
                for (int k = 0; k < 5; k++) {
                    int j = tt - k;
                    if (j >= 0 && j < 18) {
                        float wk = (k == 0) ? w0 : (k == 1) ? w1 : (k == 2) ? w2 : (k == 3) ? w3 : w4;
                        acc[j] += v * wk;
                    }
                }
            }
        } else {
            int cc = c - FDIM;
            int grp = (cc >= 40) ? 1 : 0;
            int r = cc - grp * 40;
            int se = r >> 3;
            int ee = r & 7;
            const float* s_src;
            int s_stride;
            if (se == 2) {
                s_src = rank_row + ee;
                s_stride = 8;
            } else {
                int statid = (se < 2 ? se : se - 1) + grp * 4;
                s_src = stats + statid * 8 + ee;
                s_stride = 64;
            }
            s_src += l0 * s_stride;
#pragma unroll
            for (int tt = 0; tt < 22; tt++) {
                float v = s_src[tt * s_stride];
#pragma unroll
                for (int k = 0; k < 5; k++) {
                    int j = tt - k;
                    if (j >= 0 && j < 18) {
                        float wk = (k == 0) ? w0 : (k == 1) ? w1 : (k == 2) ? w2 : (k == 3) ? w3 : w4;
                        acc[j] += v * wk;
                    }
                }
            }
        }
    }

    {
        const int w = tid >> 5;
#pragma unroll
        for (int j = 0; j < 18; j++) {
            float a = acc[j];
#pragma unroll
            for (int o = 16; o > 0; o >>= 1)
                a += __shfl_xor_sync(0xFFFFFFFFu, a, o);
            if ((tid & 31) == 0) partial[w][j] = a;
        }
    }
    __syncthreads();

    if (tid < LOUT) {
        int h2 = (tid >= 18) ? 1 : 0;
        int j = tid - h2 * 18;
        int wb = h2 * 5;
        float s = partial[wb][j] + partial[wb + 1][j] + partial[wb + 2][j] +
                  partial[wb + 3][j] + partial[wb + 4][j] + __ldg(conv_b + 127);
        float hv = (s >= 0.f) ? s : 0.01f * s;
        fin[tid] = hv * __ldg(lin_w + tid);
    }
    __syncthreads();

    if (tid == 0) {
        float s = __ldg(lin_b);
        for (int l = 0; l < LOUT; l++) s += fin[l];
        out[n] = s;
    }
}

// ---------------------------------------------------------------------------
extern "C" void kernel_launch(void* const* d_in, const int* in_sizes, int n_in,
                              void* d_out, int out_size) {
    const float* x      = (const float*)d_in[0];
    const float* conv_w = (const float*)d_in[1];
    const float* conv_b = (const float*)d_in[2];
    const float* lin_w  = (const float*)d_in[3];
    const float* lin_b  = (const float*)d_in[4];
    float* out = (float*)d_out;

    cudaFuncSetAttribute(rank_kernel, cudaFuncAttributeMaxDynamicSharedMemorySize, SMEM_R);

    rank_kernel<<<WINDOW * EE, RT, SMEM_R>>>(x);
    transpose_kernel<<<dim3((WINDOW * EE) / 32, NSTOCK / 32), dim3(32, 32)>>>();
    main_kernel<<<NSTOCK, 320>>>(x, conv_w, conv_b, lin_w, lin_b, out);
}

// round 8
// speedup vs baseline: 1.7400x; 1.0657x over previous
#include <cuda_runtime.h>
#include <cstdint>

#define WINDOW 40
#define EE 8
#define NSTOCK 8000
#define TDIM 64
#define FDIM 64
#define INCH 144
#define LOUT 36

__device__ float g_rank[WINDOW * EE * NSTOCK];      // [col][n]  (coalesced writes)
__device__ float g_rank_t[NSTOCK * WINDOW * EE];    // [n][col]  (coalesced reads in main)

// ---------------------------------------------------------------------------
// Kernel A: exact descending rank via two-level equidistributing counting.
// 512 threads. smem: h1p 8200 w | h2p 4096 w | pack 8000 w = 81184 B.
// P2's histogram atomic old-value doubles as the within-bin index, so the
// scatter needs no atomics.
// ---------------------------------------------------------------------------
#define RT 512
#define H1W 8200
#define H2W 4096
#define SMEM_R (H1W * 4 + H2W * 4 + NSTOCK * 4)

__global__ void __launch_bounds__(RT, 2) rank_kernel(const float* __restrict__ x) {
    extern __shared__ unsigned char smem_raw[];
    unsigned int* h1p  = (unsigned int*)smem_raw;                       // 16384 bins packed u16
    unsigned int* h2p  = (unsigned int*)(smem_raw + H1W * 4);           // 8192 bins packed u16
    unsigned int* pack = (unsigned int*)(smem_raw + H1W * 4 + H2W * 4); // 8000 tie-break keys

    __shared__ unsigned int wsum[16];

    const int col = blockIdx.x;
    const int tw  = col >> 3;
    const int e   = col & 7;
    const int tid = threadIdx.x;
    const unsigned int lane = tid & 31u;
    const unsigned int wid  = tid >> 5;

    // zero both histograms (uint4)
    {
        uint4 z = make_uint4(0u, 0u, 0u, 0u);
        uint4* h1v = (uint4*)h1p;
        uint4* h2v = (uint4*)h2p;
#pragma unroll
        for (int i = 0; i < 4; i++) h1v[tid + (i << 9)] = z;
#pragma unroll
        for (int i = 0; i < 2; i++) h2v[tid + (i << 9)] = z;
    }
    __syncthreads();

    const float* basep = x + (24 + tw) * FDIM + e;

    // P1: keys -> regs, level-1 histogram (top 14 bits)
    unsigned int rk[16];
#pragma unroll
    for (int i = 0; i < 16; i++) {
        int n = tid + (i << 9);
        if (n < NSTOCK) {
            unsigned int u = __float_as_uint(__ldg(basep + (size_t)n * (TDIM * FDIM)));
            u = (u & 0x80000000u) ? ~u : (u | 0x80000000u);
            rk[i] = u;
            unsigned int b = u >> 18;
            atomicAdd(&h1p[b >> 1], (b & 1u) ? 65536u : 1u);
        }
    }
    __syncthreads();

    // level-1 exclusive prefix over 16384 bins; word w -> start(2w) | start(2w+1)<<16
    {
        uint4* h1v = (uint4*)h1p;
        uint4 a[4];
        unsigned int s = 0;
#pragma unroll
        for (int j = 0; j < 4; j++) {
            a[j] = h1v[tid * 4 + j];
            s += (a[j].x & 0xFFFFu) + (a[j].x >> 16) + (a[j].y & 0xFFFFu) + (a[j].y >> 16)
               + (a[j].z & 0xFFFFu) + (a[j].z >> 16) + (a[j].w & 0xFFFFu) + (a[j].w >> 16);
        }
        unsigned int v = s;
#pragma unroll
        for (int o = 1; o < 32; o <<= 1) {
            unsigned int t = __shfl_up_sync(0xFFFFFFFFu, v, o);
            if (lane >= (unsigned)o) v += t;
        }
        if (lane == 31u) wsum[wid] = v;
        __syncthreads();
        if (wid == 0) {
            unsigned int orig = (lane < 16u) ? wsum[lane] : 0u;
            unsigned int w = orig;
#pragma unroll
            for (int o = 1; o < 32; o <<= 1) {
                unsigned int t = __shfl_up_sync(0xFFFFFFFFu, w, o);
                if (lane >= (unsigned)o) w += t;
            }
            if (lane < 16u) wsum[lane] = w - orig;
        }
        __syncthreads();
        unsigned int run = wsum[wid] + (v - s);
#pragma unroll
        for (int j = 0; j < 4; j++) {
            unsigned int* p = &a[j].x;
#pragma unroll
            for (int k = 0; k < 4; k++) {
                unsigned int w = p[k];
                unsigned int lo = w & 0xFFFFu, hi = w >> 16;
                p[k] = run | ((run + lo) << 16);
                run += lo + hi;
            }
            h1v[tid * 4 + j] = a[j];
        }
        if (tid == 0) h1p[8192] = (unsigned int)NSTOCK | ((unsigned int)NSTOCK << 16);
    }
    __syncthreads();

    // P2: level-2 bin + histogram atomic; old value = within-bin index.
    // rk[i] is re-packed as the 31-bit tie-break key K.
    unsigned int lv[16];
#pragma unroll
    for (int i = 0; i < 16; i++) {
        int n = tid + (i << 9);
        if (n < NSTOCK) {
            unsigned int u = rk[i];
            unsigned int b = u >> 18;
            unsigned int w = h1p[b >> 1];
            unsigned int s0, s1;
            if (b & 1u) { s0 = w >> 16; s1 = h1p[(b >> 1) + 1] & 0xFFFFu; }
            else        { s0 = w & 0xFFFFu; s1 = w >> 16; }
            unsigned int c = s1 - s0;
            unsigned int sub = ((u & 0x3FFFFu) * c) >> 18;
            unsigned int l2 = s0 + sub;
            unsigned int old = atomicAdd(&h2p[l2 >> 1], (l2 & 1u) ? 65536u : 1u);
            unsigned int idx = (old >> ((l2 & 1u) * 16u)) & 0xFFFFu;
            lv[i] = (l2 << 16) | idx;
            rk[i] = ((u & 0x3FFFFu) << 13) | (8191u - (unsigned)n);
        }
    }
    __syncthreads();

    // level-2 exclusive prefix over 8192 bins; word w -> start(2w) | start(2w+1)<<16
    {
        uint4* h2v = (uint4*)h2p;
        uint4 a[2];
        unsigned int s = 0;
#pragma unroll
        for (int j = 0; j < 2; j++) {
            a[j] = h2v[tid * 2 + j];
            s += (a[j].x & 0xFFFFu) + (a[j].x >> 16) + (a[j].y & 0xFFFFu) + (a[j].y >> 16)
               + (a[j].z & 0xFFFFu) + (a[j].z >> 16) + (a[j].w & 0xFFFFu) + (a[j].w >> 16);
        }
        unsigned int v = s;
#pragma unroll
        for (int o = 1; o < 32; o <<= 1) {
            unsigned int t = __shfl_up_sync(0xFFFFFFFFu, v, o);
            if (lane >= (unsigned)o) v += t;
        }
        if (lane == 31u) wsum[wid] = v;
        __syncthreads();
        if (wid == 0) {
            unsigned int orig = (lane < 16u) ? wsum[lane] : 0u;
            unsigned int w = orig;
#pragma unroll
            for (int o = 1; o < 32; o <<= 1) {
                unsigned int t = __shfl_up_sync(0xFFFFFFFFu, w, o);
                if (lane >= (unsigned)o) w += t;
            }
            if (lane < 16u) wsum[lane] = w - orig;
        }
        __syncthreads();
        unsigned int run = wsum[wid] + (v - s);
#pragma unroll
        for (int j = 0; j < 2; j++) {
            unsigned int* p = &a[j].x;
#pragma unroll
            for (int k = 0; k < 4; k++) {
                unsigned int w = p[k];
                unsigned int lo = w & 0xFFFFu, hi = w >> 16;
                p[k] = run | ((run + lo) << 16);
                run += lo + hi;
            }
            h2v[tid * 2 + j] = a[j];
        }
    }
    __syncthreads();

    // P3: scatter (no atomics): pos = start(l2) + idx
#pragma unroll
    for (int i = 0; i < 16; i++) {
        int n = tid + (i << 9);
        if (n < NSTOCK) {
            unsigned int l2 = lv[i] >> 16;
            unsigned int idx = lv[i] & 0xFFFFu;
            unsigned int w = h2p[l2 >> 1];
            unsigned int start = (w >> ((l2 & 1u) * 16u)) & 0xFFFFu;
            pack[start + idx] = rk[i];
        }
    }
    __syncthreads();

    // P4: rank = above-segment + in-segment strictly-greater; coalesced store
    float* dst = g_rank + (size_t)col * NSTOCK;
#pragma unroll
    for (int i = 0; i < 16; i++) {
        int n = tid + (i << 9);
        if (n < NSTOCK) {
            unsigned int l2 = lv[i] >> 16;
            unsigned int ws = h2p[l2 >> 1];
            unsigned int start = (ws >> ((l2 & 1u) * 16u)) & 0xFFFFu;
            unsigned int l2e = l2 + 1u;
            unsigned int we = h2p[l2e >> 1];
            unsigned int end = (we >> ((l2e & 1u) * 16u)) & 0xFFFFu;
            unsigned int K = rk[i];
            unsigned int g = (unsigned int)NSTOCK - end;
            for (unsigned int q = start; q < end; q++)
                g += (pack[q] > K) ? 1u : 0u;
            dst[n] = (float)g * (1.0f / (float)NSTOCK);
        }
    }
}

// ---------------------------------------------------------------------------
// Transpose [col][n] -> [n][col]
// ---------------------------------------------------------------------------
__global__ void transpose_kernel() {
    __shared__ float tile[32][33];
    const int c0 = blockIdx.x * 32;
    const int n0 = blockIdx.y * 32;
    const int tx = threadIdx.x, ty = threadIdx.y;
    tile[ty][tx] = g_rank[(size_t)(c0 + ty) * NSTOCK + n0 + tx];
    __syncthreads();
    g_rank_t[(size_t)(n0 + ty) * (WINDOW * EE) + c0 + tx] = tile[tx][ty];
}

// ---------------------------------------------------------------------------
// Kernel B: fused stats (single-pass) + conv (out-channel 127) + linear.
// stats layout [sid][tw][ee], sid stride 328 -> conflict-free, stride-8 reads.
// ---------------------------------------------------------------------------
#define SID_STRIDE 328

__global__ void __launch_bounds__(320) main_kernel(
    const float* __restrict__ x,
    const float* __restrict__ conv_w,
    const float* __restrict__ conv_b,
    const float* __restrict__ lin_w,
    const float* __restrict__ lin_b,
    float* __restrict__ out)
{
    __shared__ __align__(16) float xe[59][8];
    __shared__ __align__(16) float stats[8 * SID_STRIDE];
    __shared__ __align__(16) float rank_row[WINDOW * EE];
    __shared__ float partial[10][18];
    __shared__ float fin[LOUT];

    const int n = blockIdx.x;
    const int tid = threadIdx.x;
    const float* xn = x + (size_t)n * (TDIM * FDIM);

    for (int i = tid; i < 59 * 8; i += 320) {
        int tt = i >> 3, ee = i & 7;
        xe[tt][ee] = __ldg(xn + (5 + tt) * FDIM + ee);
    }
    if (tid < (WINDOW * EE) / 4) {
        const float4* rsrc = (const float4*)(g_rank_t + (size_t)n * (WINDOW * EE));
        ((float4*)rank_row)[tid] = rsrc[tid];
    }
    __syncthreads();

    // stats: one (tw, ee) task per thread, single pass (sum + sumsq + max/min)
    {
        int tw = tid >> 3, ee = tid & 7;
        int te = 19 + tw;

        float s20 = 0.f, q20 = 0.f, mx20 = -1e30f, mn20 = 1e30f;
        float s5 = 0.f, q5 = 0.f, mx5 = -1e30f, mn5 = 1e30f;
#pragma unroll
        for (int j = 0; j < 20; j++) {
            float v = xe[te - 19 + j][ee];
            s20 += v; q20 = fmaf(v, v, q20);
            mx20 = fmaxf(mx20, v); mn20 = fminf(mn20, v);
            if (j >= 15) {
                s5 += v; q5 = fmaf(v, v, q5);
                mx5 = fmaxf(mx5, v); mn5 = fminf(mn5, v);
            }
        }
        float m20 = s20 * 0.05f;
        float m5  = s5 * 0.2f;
        float sd20 = sqrtf(fmaxf(fmaf(-s20, m20, q20), 0.f) * (1.0f / 19.0f));
        float sd5  = sqrtf(fmaxf(fmaf(-s5, m5, q5), 0.f) * 0.25f);

        float* st = stats + tw * 8 + ee;
        st[0 * SID_STRIDE] = m5;   st[1 * SID_STRIDE] = sd5;
        st[2 * SID_STRIDE] = mx5;  st[3 * SID_STRIDE] = mn5;
        st[4 * SID_STRIDE] = m20;  st[5 * SID_STRIDE] = sd20;
        st[6 * SID_STRIDE] = mx20; st[7 * SID_STRIDE] = mn20;
    }
    __syncthreads();

    // conv: two threads per channel, each covering 18 of 36 outputs
    float acc[18];
#pragma unroll
    for (int j = 0; j < 18; j++) acc[j] = 0.f;

    const int hh = (tid >= 160) ? 1 : 0;
    const int c  = tid - hh * 160;
    const int l0 = hh * 18;

    if (c < INCH) {
        const float* wp = conv_w + 127 * (INCH * 5) + c * 5;
        float w0 = __ldg(wp + 0), w1 = __ldg(wp + 1), w2 = __ldg(wp + 2),
              w3 = __ldg(wp + 3), w4 = __ldg(wp + 4);

        if (c < FDIM) {
            const float* src = xn + (24 + l0) * FDIM + c;
#pragma unroll
            for (int tt = 0; tt < 22; tt++) {
                float v = __ldg(src + tt * FDIM);
#pragma unroll
                for (int k = 0; k < 5; k++) {
                    int j = tt - k;
                    if (j >= 0 && j < 18) {
                        float wk = (k == 0) ? w0 : (k == 1) ? w1 : (k == 2) ? w2 : (k == 3) ? w3 : w4;
                        acc[j] += v * wk;
                    }
                }
            }
        } else {
            int cc = c - FDIM;
            int grp = (cc >= 40) ? 1 : 0;
            int r = cc - grp * 40;
            int se = r >> 3;
            int ee = r & 7;
            const float* s_src;
            if (se == 2) {
                s_src = rank_row + ee;                                   // identical week/month
            } else {
                int statid = (se < 2 ? se : se - 1) + grp * 4;
                s_src = stats + statid * SID_STRIDE + ee;
            }
            s_src += l0 * 8;                                             // uniform stride 8
#pragma unroll
            for (int tt = 0; tt < 22; tt++) {
                float v = s_src[tt * 8];
#pragma unroll
                for (int k = 0; k < 5; k++) {
                    int j = tt - k;
                    if (j >= 0 && j < 18) {
                        float wk = (k == 0) ? w0 : (k == 1) ? w1 : (k == 2) ? w2 : (k == 3) ? w3 : w4;
                        acc[j] += v * wk;
                    }
                }
            }
        }
    }

    {
        const int w = tid >> 5;
#pragma unroll
        for (int j = 0; j < 18; j++) {
            float a = acc[j];
#pragma unroll
            for (int o = 16; o > 0; o >>= 1)
                a += __shfl_xor_sync(0xFFFFFFFFu, a, o);
            if ((tid & 31) == 0) partial[w][j] = a;
        }
    }
    __syncthreads();

    if (tid < LOUT) {
        int h2 = (tid >= 18) ? 1 : 0;
        int j = tid - h2 * 18;
        int wb = h2 * 5;
        float s = partial[wb][j] + partial[wb + 1][j] + partial[wb + 2][j] +
                  partial[wb + 3][j] + partial[wb + 4][j] + __ldg(conv_b + 127);
        float hv = (s >= 0.f) ? s : 0.01f * s;
        fin[tid] = hv * __ldg(lin_w + tid);
    }
    __syncthreads();

    if (tid == 0) {
        float s = __ldg(lin_b);
        for (int l = 0; l < LOUT; l++) s += fin[l];
        out[n] = s;
    }
}

// ---------------------------------------------------------------------------
extern "C" void kernel_launch(void* const* d_in, const int* in_sizes, int n_in,
                              void* d_out, int out_size) {
    const float* x      = (const float*)d_in[0];
    const float* conv_w = (const float*)d_in[1];
    const float* conv_b = (const float*)d_in[2];
    const float* lin_w  = (const float*)d_in[3];
    const float* lin_b  = (const float*)d_in[4];
    float* out = (float*)d_out;

    cudaFuncSetAttribute(rank_kernel, cudaFuncAttributeMaxDynamicSharedMemorySize, SMEM_R);

    rank_kernel<<<WINDOW * EE, RT, SMEM_R>>>(x);
    transpose_kernel<<<dim3((WINDOW * EE) / 32, NSTOCK / 32), dim3(32, 32)>>>();
    main_kernel<<<NSTOCK, 320>>>(x, conv_w, conv_b, lin_w, lin_b, out);
}